// round 5
// baseline (speedup 1.0000x reference)
#include <cuda_runtime.h>
#include <cuda_bf16.h>

// Problem constants (fixed by the reference)
#define NNODES 50000
#define NEDGES 800000
#define NFEAT  512
#define NHID   256
#define NLAT   128

// ---------------- scratch (device globals; no allocation allowed) -----------
static __device__ float g_C1[(size_t)NNODES * NHID];   // x@W1
static __device__ float g_H [(size_t)NNODES * NHID];   // relu(spmm1+b1)
static __device__ float g_C2[(size_t)NNODES * NLAT];   // h@W2
static __device__ int   g_rowptr[NNODES + 1];
static __device__ int   g_cnt[NNODES];
static __device__ int   g_cols[NEDGES];
static __device__ float g_vals[NEDGES];

// ---------------- CSR build --------------------------------------------------
__global__ void zero_cnt_kernel() {
    int i = blockIdx.x * blockDim.x + threadIdx.x;
    if (i < NNODES) g_cnt[i] = 0;
}

__global__ void hist_kernel(const int* __restrict__ rows) {
    int e = blockIdx.x * blockDim.x + threadIdx.x;
    if (e < NEDGES) atomicAdd(&g_cnt[rows[e]], 1);
}

// Single-block exclusive scan of g_cnt -> g_rowptr, also resets g_cnt (cursor).
__global__ void scan_kernel() {
    __shared__ int sums[256];
    int tid = threadIdx.x;
    const int chunk = (NNODES + 255) / 256;
    int s0 = tid * chunk;
    int s1 = min(s0 + chunk, NNODES);
    int s = 0;
    for (int i = s0; i < s1; i++) s += g_cnt[i];
    sums[tid] = s;
    __syncthreads();
    if (tid == 0) {
        int acc = 0;
        for (int i = 0; i < 256; i++) { int t = sums[i]; sums[i] = acc; acc += t; }
        g_rowptr[NNODES] = acc;
    }
    __syncthreads();
    int acc = sums[tid];
    for (int i = s0; i < s1; i++) {
        g_rowptr[i] = acc;
        acc += g_cnt[i];
        g_cnt[i] = 0;   // reset as scatter cursor
    }
}

__global__ void scatter_kernel(const int* __restrict__ rows, const int* __restrict__ cols,
                               const float* __restrict__ vals) {
    int e = blockIdx.x * blockDim.x + threadIdx.x;
    if (e >= NEDGES) return;
    int r = rows[e];
    int p = g_rowptr[r] + atomicAdd(&g_cnt[r], 1);
    g_cols[p] = cols[e];
    g_vals[p] = vals[e];
}

// ---------------- SGEMM 128x128x8, 8x8 microtile, reg-prefetch --------------
#define GBM 128
#define GBN 128
#define GBK 8

__global__ __launch_bounds__(256) void sgemm_kernel(
    const float* __restrict__ A, const float* __restrict__ B, float* __restrict__ C,
    int M, int N, int K)
{
    __shared__ float As[GBK][GBM];   // transposed A tile
    __shared__ float Bs[GBK][GBN];

    const int tid = threadIdx.x;               // 256 threads
    const int bm = blockIdx.y * GBM;
    const int bn = blockIdx.x * GBN;

    // global->smem load mapping
    const int arow = tid >> 1;                 // 0..127
    const int acol = (tid & 1) * 4;            // 0 or 4
    const int brow = tid >> 5;                 // 0..7
    const int bcol = (tid & 31) * 4;           // 0..124

    // compute mapping: 8 warps as 2x4 (m x n), lanes as 8x4
    const int w = tid >> 5, l = tid & 31;
    const int wm = w >> 2, wn = w & 3;
    const int lm = l >> 2, ln = l & 3;
    const int mbase = wm * 64 + lm * 4;        // + {0, 32}
    const int nbase = wn * 32 + ln * 4;        // + {0, 16}

    float acc[8][8];
#pragma unroll
    for (int i = 0; i < 8; i++)
#pragma unroll
        for (int j = 0; j < 8; j++) acc[i][j] = 0.f;

    // prefetch first tile into registers
    float4 pa = make_float4(0.f, 0.f, 0.f, 0.f);
    float4 pb;
    {
        int r = bm + arow;
        if (r < M) pa = *(const float4*)&A[(size_t)r * K + acol];
        pb = *(const float4*)&B[(size_t)brow * N + bn + bcol];
    }

    for (int k0 = 0; k0 < K; k0 += GBK) {
        As[acol + 0][arow] = pa.x;
        As[acol + 1][arow] = pa.y;
        As[acol + 2][arow] = pa.z;
        As[acol + 3][arow] = pa.w;
        *(float4*)&Bs[brow][bcol] = pb;
        __syncthreads();

        if (k0 + GBK < K) {
            int r = bm + arow;
            pa = make_float4(0.f, 0.f, 0.f, 0.f);
            if (r < M) pa = *(const float4*)&A[(size_t)r * K + (k0 + GBK) + acol];
            pb = *(const float4*)&B[(size_t)(k0 + GBK + brow) * N + bn + bcol];
        }

#pragma unroll
        for (int k = 0; k < GBK; k++) {
            float4 a0 = *(const float4*)&As[k][mbase];
            float4 a1 = *(const float4*)&As[k][mbase + 32];
            float4 b0 = *(const float4*)&Bs[k][nbase];
            float4 b1 = *(const float4*)&Bs[k][nbase + 16];
            float av[8] = {a0.x, a0.y, a0.z, a0.w, a1.x, a1.y, a1.z, a1.w};
            float bv[8] = {b0.x, b0.y, b0.z, b0.w, b1.x, b1.y, b1.z, b1.w};
#pragma unroll
            for (int i = 0; i < 8; i++)
#pragma unroll
                for (int j = 0; j < 8; j++)
                    acc[i][j] = fmaf(av[i], bv[j], acc[i][j]);
        }
        __syncthreads();
    }

#pragma unroll
    for (int i = 0; i < 8; i++) {
        int m = bm + mbase + ((i < 4) ? i : (32 + i - 4));
        if (m < M) {
            float4 o0 = make_float4(acc[i][0], acc[i][1], acc[i][2], acc[i][3]);
            float4 o1 = make_float4(acc[i][4], acc[i][5], acc[i][6], acc[i][7]);
            *(float4*)&C[(size_t)m * N + bn + nbase] = o0;
            *(float4*)&C[(size_t)m * N + bn + nbase + 16] = o1;
        }
    }
}

// ---------------- CSR SpMM with fused bias+relu -----------------------------
// One warp per output row; register accumulation; 2-edge unroll so the two
// row-gathers are in flight simultaneously (2x MLP on the latency-exposed
// random gather). NP = number of 128-float passes (d = NP*128).
template <int NP>
__global__ __launch_bounds__(256) void spmm_kernel(
    const float* __restrict__ dense, const float* __restrict__ bias,
    float* __restrict__ out)
{
    int gw = (blockIdx.x * blockDim.x + threadIdx.x) >> 5;
    int lane = threadIdx.x & 31;
    if (gw >= NNODES) return;
    const int d = NP * 128;

    int beg = g_rowptr[gw];
    int end = g_rowptr[gw + 1];

    float4 acc[NP];
#pragma unroll
    for (int p = 0; p < NP; p++) acc[p] = make_float4(0.f, 0.f, 0.f, 0.f);

    int e = beg;
    for (; e + 1 < end; e += 2) {
        int   c0 = __ldg(&g_cols[e]);
        int   c1 = __ldg(&g_cols[e + 1]);
        float v0 = __ldg(&g_vals[e]);
        float v1 = __ldg(&g_vals[e + 1]);
        const float4* s0 = (const float4*)&dense[(size_t)c0 * d];
        const float4* s1 = (const float4*)&dense[(size_t)c1 * d];
        float4 t0[NP], t1[NP];
#pragma unroll
        for (int p = 0; p < NP; p++) t0[p] = __ldg(&s0[lane + 32 * p]);
#pragma unroll
        for (int p = 0; p < NP; p++) t1[p] = __ldg(&s1[lane + 32 * p]);
#pragma unroll
        for (int p = 0; p < NP; p++) {
            acc[p].x = fmaf(v0, t0[p].x, acc[p].x);
            acc[p].y = fmaf(v0, t0[p].y, acc[p].y);
            acc[p].z = fmaf(v0, t0[p].z, acc[p].z);
            acc[p].w = fmaf(v0, t0[p].w, acc[p].w);
            acc[p].x = fmaf(v1, t1[p].x, acc[p].x);
            acc[p].y = fmaf(v1, t1[p].y, acc[p].y);
            acc[p].z = fmaf(v1, t1[p].z, acc[p].z);
            acc[p].w = fmaf(v1, t1[p].w, acc[p].w);
        }
    }
    if (e < end) {
        int   c = __ldg(&g_cols[e]);
        float v = __ldg(&g_vals[e]);
        const float4* s = (const float4*)&dense[(size_t)c * d];
#pragma unroll
        for (int p = 0; p < NP; p++) {
            float4 t = __ldg(&s[lane + 32 * p]);
            acc[p].x = fmaf(v, t.x, acc[p].x);
            acc[p].y = fmaf(v, t.y, acc[p].y);
            acc[p].z = fmaf(v, t.z, acc[p].z);
            acc[p].w = fmaf(v, t.w, acc[p].w);
        }
    }

    const float4* bp = (const float4*)bias;
    float4* op = (float4*)&out[(size_t)gw * d];
#pragma unroll
    for (int p = 0; p < NP; p++) {
        float4 b = __ldg(&bp[lane + 32 * p]);
        float4 r;
        r.x = fmaxf(acc[p].x + b.x, 0.f);
        r.y = fmaxf(acc[p].y + b.y, 0.f);
        r.z = fmaxf(acc[p].z + b.z, 0.f);
        r.w = fmaxf(acc[p].w + b.w, 0.f);
        op[lane + 32 * p] = r;
    }
}

// ---------------- launch -----------------------------------------------------
// Launch order is chosen so that launches #3 and #4 (0-indexed) are the two
// halves of GEMM1 — R3's capture landed ~2 launches offset into my stream,
// so slots 3/4 should put a GEMM half into the ncu window this round.
extern "C" void kernel_launch(void* const* d_in, const int* in_sizes, int n_in,
                              void* d_out, int out_size)
{
    const float* x    = (const float*)d_in[0];
    const int*   rows = (const int*)  d_in[1];
    const int*   cols = (const int*)  d_in[2];
    const float* vals = (const float*)d_in[3];
    const float* W1   = (const float*)d_in[4];
    const float* b1   = (const float*)d_in[5];
    const float* W2   = (const float*)d_in[6];
    const float* b2   = (const float*)d_in[7];
    float* out = (float*)d_out;

    (void)in_sizes; (void)n_in; (void)out_size;

    const int M1 = 25088;              // 196 blocks of 128
    const int M2 = NNODES - M1;        // 24912 -> 195 blocks

    // #0..#2: CSR histogram + scan
    zero_cnt_kernel<<<(NNODES + 255) / 256, 256>>>();
    hist_kernel<<<(NEDGES + 255) / 256, 256>>>(rows);
    scan_kernel<<<1, 256>>>();

    // #3, #4: GEMM1 = x @ W1, split in M so a half lands in the ncu slot
    {
        dim3 grid1(NHID / GBN, (M1 + GBM - 1) / GBM);
        sgemm_kernel<<<grid1, 256>>>(x, W1, g_C1, M1, NHID, NFEAT);
        dim3 grid2(NHID / GBN, (M2 + GBM - 1) / GBM);
        sgemm_kernel<<<grid2, 256>>>(x + (size_t)M1 * NFEAT, W1,
                                     g_C1 + (size_t)M1 * NHID, M2, NHID, NFEAT);
    }

    // #5: CSR scatter (needs scan; independent of GEMM1)
    scatter_kernel<<<(NEDGES + 255) / 256, 256>>>(rows, cols, vals);

    // #6: H = relu(spmm(C1) + b1)
    spmm_kernel<2><<<(NNODES * 32 + 255) / 256, 256>>>(g_C1, b1, g_H);

    // #7: C2 = H @ W2
    {
        dim3 grid(NLAT / GBN, (NNODES + GBM - 1) / GBM);
        sgemm_kernel<<<grid, 256>>>(g_H, W2, g_C2, NNODES, NLAT, NHID);
    }

    // #8: out = relu(spmm(C2) + b2)
    spmm_kernel<1><<<(NNODES * 32 + 255) / 256, 256>>>(g_C2, b2, out);
}

// round 7
// speedup vs baseline: 1.0069x; 1.0069x over previous
#include <cuda_runtime.h>
#include <cuda_bf16.h>

// Problem constants (fixed by the reference)
#define NNODES 50000
#define NEDGES 800000
#define NFEAT  512
#define NHID   256
#define NLAT   128

// ---------------- scratch (device globals; no allocation allowed) -----------
static __device__ float g_C1[(size_t)NNODES * NHID];   // x@W1
static __device__ float g_H [(size_t)NNODES * NHID];   // relu(spmm1+b1)
static __device__ float g_C2[(size_t)NNODES * NLAT];   // h@W2
static __device__ int   g_rowptr[NNODES + 1];
static __device__ int   g_cnt[NNODES];
static __device__ int   g_cols[NEDGES];
static __device__ float g_vals[NEDGES];

// ---------------- CSR build --------------------------------------------------
__global__ void zero_cnt_kernel() {
    int i = blockIdx.x * blockDim.x + threadIdx.x;
    if (i < NNODES) g_cnt[i] = 0;
}

__global__ void hist_kernel(const int* __restrict__ rows) {
    int e = blockIdx.x * blockDim.x + threadIdx.x;
    if (e < NEDGES) atomicAdd(&g_cnt[rows[e]], 1);
}

// Single-block exclusive scan of g_cnt -> g_rowptr, also resets g_cnt (cursor).
__global__ void scan_kernel() {
    __shared__ int sums[256];
    int tid = threadIdx.x;
    const int chunk = (NNODES + 255) / 256;
    int s0 = tid * chunk;
    int s1 = min(s0 + chunk, NNODES);
    int s = 0;
    for (int i = s0; i < s1; i++) s += g_cnt[i];
    sums[tid] = s;
    __syncthreads();
    if (tid == 0) {
        int acc = 0;
        for (int i = 0; i < 256; i++) { int t = sums[i]; sums[i] = acc; acc += t; }
        g_rowptr[NNODES] = acc;
    }
    __syncthreads();
    int acc = sums[tid];
    for (int i = s0; i < s1; i++) {
        g_rowptr[i] = acc;
        acc += g_cnt[i];
        g_cnt[i] = 0;   // reset as scatter cursor
    }
}

__global__ void scatter_kernel(const int* __restrict__ rows, const int* __restrict__ cols,
                               const float* __restrict__ vals) {
    int e = blockIdx.x * blockDim.x + threadIdx.x;
    if (e >= NEDGES) return;
    int r = rows[e];
    int p = g_rowptr[r] + atomicAdd(&g_cnt[r], 1);
    g_cols[p] = cols[e];
    g_vals[p] = vals[e];
}

// ---------------- SGEMM 128x128x8, 8x8 microtile, reg-prefetch --------------
#define GBM 128
#define GBN 128
#define GBK 8

__global__ __launch_bounds__(256) void sgemm_kernel(
    const float* __restrict__ A, const float* __restrict__ B, float* __restrict__ C,
    int M, int N, int K)
{
    __shared__ float As[GBK][GBM];   // transposed A tile
    __shared__ float Bs[GBK][GBN];

    const int tid = threadIdx.x;               // 256 threads
    const int bm = blockIdx.y * GBM;
    const int bn = blockIdx.x * GBN;

    // global->smem load mapping
    const int arow = tid >> 1;                 // 0..127
    const int acol = (tid & 1) * 4;            // 0 or 4
    const int brow = tid >> 5;                 // 0..7
    const int bcol = (tid & 31) * 4;           // 0..124

    // compute mapping: 8 warps as 2x4 (m x n), lanes as 8x4
    const int w = tid >> 5, l = tid & 31;
    const int wm = w >> 2, wn = w & 3;
    const int lm = l >> 2, ln = l & 3;
    const int mbase = wm * 64 + lm * 4;        // + {0, 32}
    const int nbase = wn * 32 + ln * 4;        // + {0, 16}

    float acc[8][8];
#pragma unroll
    for (int i = 0; i < 8; i++)
#pragma unroll
        for (int j = 0; j < 8; j++) acc[i][j] = 0.f;

    // prefetch first tile into registers
    float4 pa = make_float4(0.f, 0.f, 0.f, 0.f);
    float4 pb;
    {
        int r = bm + arow;
        if (r < M) pa = *(const float4*)&A[(size_t)r * K + acol];
        pb = *(const float4*)&B[(size_t)brow * N + bn + bcol];
    }

    for (int k0 = 0; k0 < K; k0 += GBK) {
        As[acol + 0][arow] = pa.x;
        As[acol + 1][arow] = pa.y;
        As[acol + 2][arow] = pa.z;
        As[acol + 3][arow] = pa.w;
        *(float4*)&Bs[brow][bcol] = pb;
        __syncthreads();

        if (k0 + GBK < K) {
            int r = bm + arow;
            pa = make_float4(0.f, 0.f, 0.f, 0.f);
            if (r < M) pa = *(const float4*)&A[(size_t)r * K + (k0 + GBK) + acol];
            pb = *(const float4*)&B[(size_t)(k0 + GBK + brow) * N + bn + bcol];
        }

#pragma unroll
        for (int k = 0; k < GBK; k++) {
            float4 a0 = *(const float4*)&As[k][mbase];
            float4 a1 = *(const float4*)&As[k][mbase + 32];
            float4 b0 = *(const float4*)&Bs[k][nbase];
            float4 b1 = *(const float4*)&Bs[k][nbase + 16];
            float av[8] = {a0.x, a0.y, a0.z, a0.w, a1.x, a1.y, a1.z, a1.w};
            float bv[8] = {b0.x, b0.y, b0.z, b0.w, b1.x, b1.y, b1.z, b1.w};
#pragma unroll
            for (int i = 0; i < 8; i++)
#pragma unroll
                for (int j = 0; j < 8; j++)
                    acc[i][j] = fmaf(av[i], bv[j], acc[i][j]);
        }
        __syncthreads();
    }

#pragma unroll
    for (int i = 0; i < 8; i++) {
        int m = bm + mbase + ((i < 4) ? i : (32 + i - 4));
        if (m < M) {
            float4 o0 = make_float4(acc[i][0], acc[i][1], acc[i][2], acc[i][3]);
            float4 o1 = make_float4(acc[i][4], acc[i][5], acc[i][6], acc[i][7]);
            *(float4*)&C[(size_t)m * N + bn + nbase] = o0;
            *(float4*)&C[(size_t)m * N + bn + nbase + 16] = o1;
        }
    }
}

// ---------------- CSR SpMM, latency-optimized --------------------------------
// NSLICE warps per row, each covering a 128-float feature slice (1 LDG.128
// per lane per edge). 4-edge batches: 4 independent gathers in flight per
// warp, index loads pipelined ahead of the gather chain. Tail edges padded
// with c=0, v=0 (harmless gather of row 0). Fused bias+relu epilogue.
template <int NSLICE>
__global__ __launch_bounds__(256) void spmm_kernel(
    const float* __restrict__ dense, const float* __restrict__ bias,
    float* __restrict__ out)
{
    int gw = (blockIdx.x * blockDim.x + threadIdx.x) >> 5;
    int lane = threadIdx.x & 31;
    int row = gw / NSLICE;
    int slice = gw % NSLICE;
    if (row >= NNODES) return;
    const int d = NSLICE * 128;
    const int soff = slice * 128 + lane * 4;

    int beg = __ldg(&g_rowptr[row]);
    int end = __ldg(&g_rowptr[row + 1]);

    float4 acc = make_float4(0.f, 0.f, 0.f, 0.f);

    for (int e = beg; e < end; e += 4) {
        int   c0 = __ldg(&g_cols[e]);
        float v0 = __ldg(&g_vals[e]);
        int   c1 = 0, c2 = 0, c3 = 0;
        float v1 = 0.f, v2 = 0.f, v3 = 0.f;
        if (e + 1 < end) { c1 = __ldg(&g_cols[e + 1]); v1 = __ldg(&g_vals[e + 1]); }
        if (e + 2 < end) { c2 = __ldg(&g_cols[e + 2]); v2 = __ldg(&g_vals[e + 2]); }
        if (e + 3 < end) { c3 = __ldg(&g_cols[e + 3]); v3 = __ldg(&g_vals[e + 3]); }

        float4 t0 = __ldg((const float4*)&dense[(size_t)c0 * d + soff]);
        float4 t1 = __ldg((const float4*)&dense[(size_t)c1 * d + soff]);
        float4 t2 = __ldg((const float4*)&dense[(size_t)c2 * d + soff]);
        float4 t3 = __ldg((const float4*)&dense[(size_t)c3 * d + soff]);

        acc.x = fmaf(v0, t0.x, fmaf(v1, t1.x, fmaf(v2, t2.x, fmaf(v3, t3.x, acc.x))));
        acc.y = fmaf(v0, t0.y, fmaf(v1, t1.y, fmaf(v2, t2.y, fmaf(v3, t3.y, acc.y))));
        acc.z = fmaf(v0, t0.z, fmaf(v1, t1.z, fmaf(v2, t2.z, fmaf(v3, t3.z, acc.z))));
        acc.w = fmaf(v0, t0.w, fmaf(v1, t1.w, fmaf(v2, t2.w, fmaf(v3, t3.w, acc.w))));
    }

    float4 b = __ldg((const float4*)&bias[soff]);
    float4 r;
    r.x = fmaxf(acc.x + b.x, 0.f);
    r.y = fmaxf(acc.y + b.y, 0.f);
    r.z = fmaxf(acc.z + b.z, 0.f);
    r.w = fmaxf(acc.w + b.w, 0.f);
    *(float4*)&out[(size_t)row * d + soff] = r;
}

// ---------------- launch -----------------------------------------------------
// Slot layout keeps gemm1a at my launch index 3 (the ncu -s 5 window lands
// there given the ~2 harness-side launches) as a profiled control.
extern "C" void kernel_launch(void* const* d_in, const int* in_sizes, int n_in,
                              void* d_out, int out_size)
{
    const float* x    = (const float*)d_in[0];
    const int*   rows = (const int*)  d_in[1];
    const int*   cols = (const int*)  d_in[2];
    const float* vals = (const float*)d_in[3];
    const float* W1   = (const float*)d_in[4];
    const float* b1   = (const float*)d_in[5];
    const float* W2   = (const float*)d_in[6];
    const float* b2   = (const float*)d_in[7];
    float* out = (float*)d_out;

    (void)in_sizes; (void)n_in; (void)out_size;

    const int M1 = 25088;              // 196 blocks of 128
    const int M2 = NNODES - M1;        // 24912 -> 195 blocks

    // #0..#2: CSR histogram + scan
    zero_cnt_kernel<<<(NNODES + 255) / 256, 256>>>();
    hist_kernel<<<(NEDGES + 255) / 256, 256>>>(rows);
    scan_kernel<<<1, 256>>>();

    // #3, #4: GEMM1 = x @ W1 (slot 3 is the profiled control)
    {
        dim3 grid1(NHID / GBN, (M1 + GBM - 1) / GBM);
        sgemm_kernel<<<grid1, 256>>>(x, W1, g_C1, M1, NHID, NFEAT);
        dim3 grid2(NHID / GBN, (M2 + GBM - 1) / GBM);
        sgemm_kernel<<<grid2, 256>>>(x + (size_t)M1 * NFEAT, W1,
                                     g_C1 + (size_t)M1 * NHID, M2, NHID, NFEAT);
    }

    // #5: CSR scatter
    scatter_kernel<<<(NEDGES + 255) / 256, 256>>>(rows, cols, vals);

    // #6: H = relu(spmm(C1) + b1)   (2 warps per row)
    {
        long long warps = (long long)NNODES * 2;
        int blocks = (int)((warps * 32 + 255) / 256);
        spmm_kernel<2><<<blocks, 256>>>(g_C1, b1, g_H);
    }

    // #7: C2 = H @ W2
    {
        dim3 grid(NLAT / GBN, (NNODES + GBM - 1) / GBM);
        sgemm_kernel<<<grid, 256>>>(g_H, W2, g_C2, NNODES, NLAT, NHID);
    }

    // #8: out = relu(spmm(C2) + b2)  (1 warp per row)
    {
        long long warps = (long long)NNODES;
        int blocks = (int)((warps * 32 + 255) / 256);
        spmm_kernel<1><<<blocks, 256>>>(g_C2, b2, out);
    }
}

// round 10
// speedup vs baseline: 1.0955x; 1.0880x over previous
#include <cuda_runtime.h>
#include <cuda_bf16.h>

// Problem constants (fixed by the reference)
#define NNODES 50000
#define NEDGES 800000
#define NFEAT  512
#define NHID   256
#define NLAT   128

// ---------------- scratch (device globals; no allocation allowed) -----------
static __device__ float g_C1[(size_t)NNODES * NHID];   // x@W1
static __device__ float g_H [(size_t)NNODES * NHID];   // relu(spmm1+b1)
static __device__ float g_C2[(size_t)NNODES * NLAT];   // h@W2
static __device__ int   g_rowptr[NNODES + 1];
static __device__ int   g_cnt[NNODES];                 // statically zero-initialized
static __device__ int   g_cols[NEDGES];
static __device__ float g_vals[NEDGES];

// ---------------- CSR build --------------------------------------------------
// g_cnt is zero at first call (static init) and restored to zero by the
// countdown scatter at the end of every call — no zeroing kernel needed.
__global__ void hist_kernel(const int* __restrict__ rows) {
    int e = blockIdx.x * blockDim.x + threadIdx.x;
    if (e < NEDGES) atomicAdd(&g_cnt[rows[e]], 1);
}

// Single-block exclusive scan of g_cnt -> g_rowptr. Does NOT reset g_cnt
// (degrees are needed as countdown cursors by the scatter).
__global__ void scan_kernel() {
    __shared__ int sums[256];
    int tid = threadIdx.x;
    const int chunk = (NNODES + 255) / 256;
    int s0 = tid * chunk;
    int s1 = min(s0 + chunk, NNODES);
    int s = 0;
    for (int i = s0; i < s1; i++) s += g_cnt[i];
    sums[tid] = s;
    __syncthreads();
    if (tid == 0) {
        int acc = 0;
        for (int i = 0; i < 256; i++) { int t = sums[i]; sums[i] = acc; acc += t; }
        g_rowptr[NNODES] = acc;
    }
    __syncthreads();
    int acc = sums[tid];
    for (int i = s0; i < s1; i++) {
        g_rowptr[i] = acc;
        acc += g_cnt[i];
    }
}

// ---------------- SGEMM core (device fn), 128x128x8, 8x8 microtile ----------
#define GBM 128
#define GBN 128
#define GBK 8

__device__ __forceinline__ void sgemm_device(
    const float* __restrict__ A, const float* __restrict__ B, float* __restrict__ C,
    int M, int N, int K, int bx, int by,
    float (*As)[GBM], float (*Bs)[GBN])
{
    const int tid = threadIdx.x;               // 256 threads
    const int bm = by * GBM;
    const int bn = bx * GBN;

    const int arow = tid >> 1;                 // 0..127
    const int acol = (tid & 1) * 4;            // 0 or 4
    const int brow = tid >> 5;                 // 0..7
    const int bcol = (tid & 31) * 4;           // 0..124

    const int w = tid >> 5, l = tid & 31;
    const int wm = w >> 2, wn = w & 3;
    const int lm = l >> 2, ln = l & 3;
    const int mbase = wm * 64 + lm * 4;        // + {0, 32}
    const int nbase = wn * 32 + ln * 4;        // + {0, 16}

    float acc[8][8];
#pragma unroll
    for (int i = 0; i < 8; i++)
#pragma unroll
        for (int j = 0; j < 8; j++) acc[i][j] = 0.f;

    float4 pa = make_float4(0.f, 0.f, 0.f, 0.f);
    float4 pb;
    {
        int r = bm + arow;
        if (r < M) pa = *(const float4*)&A[(size_t)r * K + acol];
        pb = *(const float4*)&B[(size_t)brow * N + bn + bcol];
    }

    for (int k0 = 0; k0 < K; k0 += GBK) {
        As[acol + 0][arow] = pa.x;
        As[acol + 1][arow] = pa.y;
        As[acol + 2][arow] = pa.z;
        As[acol + 3][arow] = pa.w;
        *(float4*)&Bs[brow][bcol] = pb;
        __syncthreads();

        if (k0 + GBK < K) {
            int r = bm + arow;
            pa = make_float4(0.f, 0.f, 0.f, 0.f);
            if (r < M) pa = *(const float4*)&A[(size_t)r * K + (k0 + GBK) + acol];
            pb = *(const float4*)&B[(size_t)(k0 + GBK + brow) * N + bn + bcol];
        }

#pragma unroll
        for (int k = 0; k < GBK; k++) {
            float4 a0 = *(const float4*)&As[k][mbase];
            float4 a1 = *(const float4*)&As[k][mbase + 32];
            float4 b0 = *(const float4*)&Bs[k][nbase];
            float4 b1 = *(const float4*)&Bs[k][nbase + 16];
            float av[8] = {a0.x, a0.y, a0.z, a0.w, a1.x, a1.y, a1.z, a1.w};
            float bv[8] = {b0.x, b0.y, b0.z, b0.w, b1.x, b1.y, b1.z, b1.w};
#pragma unroll
            for (int i = 0; i < 8; i++)
#pragma unroll
                for (int j = 0; j < 8; j++)
                    acc[i][j] = fmaf(av[i], bv[j], acc[i][j]);
        }
        __syncthreads();
    }

#pragma unroll
    for (int i = 0; i < 8; i++) {
        int m = bm + mbase + ((i < 4) ? i : (32 + i - 4));
        if (m < M) {
            float4 o0 = make_float4(acc[i][0], acc[i][1], acc[i][2], acc[i][3]);
            float4 o1 = make_float4(acc[i][4], acc[i][5], acc[i][6], acc[i][7]);
            *(float4*)&C[(size_t)m * N + bn + nbase] = o0;
            *(float4*)&C[(size_t)m * N + bn + nbase + 16] = o1;
        }
    }
}

__global__ __launch_bounds__(256) void sgemm_kernel(
    const float* __restrict__ A, const float* __restrict__ B, float* __restrict__ C,
    int M, int N, int K)
{
    __shared__ float As[GBK][GBM];
    __shared__ float Bs[GBK][GBN];
    sgemm_device(A, B, C, M, N, K, blockIdx.x, blockIdx.y, As, Bs);
}

// ---------------- fat kernel: gemm1 tiles + countdown scatter ---------------
#define GEMM1_BX (NHID / GBN)                       // 2
#define GEMM1_BY ((NNODES + GBM - 1) / GBM)         // 391
#define GEMM1_BLOCKS (GEMM1_BX * GEMM1_BY)          // 782
#define SCAT_BLOCKS ((NEDGES + 255) / 256)          // 3125

__global__ __launch_bounds__(256) void mega_kernel(
    const float* __restrict__ A, const float* __restrict__ B, float* __restrict__ C,
    const int* __restrict__ rows, const int* __restrict__ cols,
    const float* __restrict__ vals)
{
    __shared__ float As[GBK][GBM];
    __shared__ float Bs[GBK][GBN];
    if (blockIdx.x < GEMM1_BLOCKS) {
        sgemm_device(A, B, C, NNODES, NHID, NFEAT,
                     blockIdx.x % GEMM1_BX, blockIdx.x / GEMM1_BX, As, Bs);
    } else {
        int e = (blockIdx.x - GEMM1_BLOCKS) * 256 + threadIdx.x;
        if (e < NEDGES) {
            int r = rows[e];
            int k = atomicSub(&g_cnt[r], 1) - 1;   // ends at 0 -> ready for next call
            int p = g_rowptr[r] + k;
            g_cols[p] = cols[e];
            g_vals[p] = vals[e];
        }
    }
}

// ---------------- CSR SpMM (identical to R7 for clean measurement) ----------
template <int NSLICE>
__global__ __launch_bounds__(256) void spmm_kernel(
    const float* __restrict__ dense, const float* __restrict__ bias,
    float* __restrict__ out)
{
    int gw = (blockIdx.x * blockDim.x + threadIdx.x) >> 5;
    int lane = threadIdx.x & 31;
    int row = gw / NSLICE;
    int slice = gw % NSLICE;
    if (row >= NNODES) return;
    const int d = NSLICE * 128;
    const int soff = slice * 128 + lane * 4;

    int beg = __ldg(&g_rowptr[row]);
    int end = __ldg(&g_rowptr[row + 1]);

    float4 acc = make_float4(0.f, 0.f, 0.f, 0.f);

    for (int e = beg; e < end; e += 4) {
        int   c0 = __ldg(&g_cols[e]);
        float v0 = __ldg(&g_vals[e]);
        int   c1 = 0, c2 = 0, c3 = 0;
        float v1 = 0.f, v2 = 0.f, v3 = 0.f;
        if (e + 1 < end) { c1 = __ldg(&g_cols[e + 1]); v1 = __ldg(&g_vals[e + 1]); }
        if (e + 2 < end) { c2 = __ldg(&g_cols[e + 2]); v2 = __ldg(&g_vals[e + 2]); }
        if (e + 3 < end) { c3 = __ldg(&g_cols[e + 3]); v3 = __ldg(&g_vals[e + 3]); }

        float4 t0 = __ldg((const float4*)&dense[(size_t)c0 * d + soff]);
        float4 t1 = __ldg((const float4*)&dense[(size_t)c1 * d + soff]);
        float4 t2 = __ldg((const float4*)&dense[(size_t)c2 * d + soff]);
        float4 t3 = __ldg((const float4*)&dense[(size_t)c3 * d + soff]);

        acc.x = fmaf(v0, t0.x, fmaf(v1, t1.x, fmaf(v2, t2.x, fmaf(v3, t3.x, acc.x))));
        acc.y = fmaf(v0, t0.y, fmaf(v1, t1.y, fmaf(v2, t2.y, fmaf(v3, t3.y, acc.y))));
        acc.z = fmaf(v0, t0.z, fmaf(v1, t1.z, fmaf(v2, t2.z, fmaf(v3, t3.z, acc.z))));
        acc.w = fmaf(v0, t0.w, fmaf(v1, t1.w, fmaf(v2, t2.w, fmaf(v3, t3.w, acc.w))));
    }

    float4 b = __ldg((const float4*)&bias[soff]);
    float4 r;
    r.x = fmaxf(acc.x + b.x, 0.f);
    r.y = fmaxf(acc.y + b.y, 0.f);
    r.z = fmaxf(acc.z + b.z, 0.f);
    r.w = fmaxf(acc.w + b.w, 0.f);
    *(float4*)&out[(size_t)row * d + soff] = r;
}

// ---------------- launch -----------------------------------------------------
// The ncu capture reliably hits MY launch index 3 (3 rounds of evidence).
// This round slot 3 = spmm1 — the never-yet-measured suspect.
extern "C" void kernel_launch(void* const* d_in, const int* in_sizes, int n_in,
                              void* d_out, int out_size)
{
    const float* x    = (const float*)d_in[0];
    const int*   rows = (const int*)  d_in[1];
    const int*   cols = (const int*)  d_in[2];
    const float* vals = (const float*)d_in[3];
    const float* W1   = (const float*)d_in[4];
    const float* b1   = (const float*)d_in[5];
    const float* W2   = (const float*)d_in[6];
    const float* b2   = (const float*)d_in[7];
    float* out = (float*)d_out;

    (void)in_sizes; (void)n_in; (void)out_size;

    // #0: degree histogram (g_cnt starts zero: static init / countdown restore)
    hist_kernel<<<(NEDGES + 255) / 256, 256>>>(rows);

    // #1: exclusive scan -> rowptr (keeps g_cnt = degrees)
    scan_kernel<<<1, 256>>>();

    // #2: fat kernel: gemm1 (x@W1 -> g_C1) + countdown scatter (CSR cols/vals)
    mega_kernel<<<GEMM1_BLOCKS + SCAT_BLOCKS, 256>>>(x, W1, g_C1, rows, cols, vals);

    // #3: H = relu(spmm(C1) + b1)   (2 warps per row)  <-- PROFILED SLOT
    {
        int blocks = (NNODES * 2 + 7) / 8;   // 8 warps per block
        spmm_kernel<2><<<blocks, 256>>>(g_C1, b1, g_H);
    }

    // #4: C2 = H @ W2
    {
        dim3 grid(NLAT / GBN, (NNODES + GBM - 1) / GBM);
        sgemm_kernel<<<grid, 256>>>(g_H, W2, g_C2, NNODES, NLAT, NHID);
    }

    // #5: out = relu(spmm(C2) + b2)  (1 warp per row)
    {
        int blocks = (NNODES + 7) / 8;
        spmm_kernel<1><<<blocks, 256>>>(g_C2, b2, out);
    }
}